// round 4
// baseline (speedup 1.0000x reference)
#include <cuda_runtime.h>
#include <cstddef>

#define BB 16
#define SS 512
#define DD 384

// Inclusive cumsum of durations per batch. 16*512*4 = 32 KB scratch.
__device__ int g_csum[BB * SS];

// One block per batch, 512 threads = 16 warps. shfl warp scan + block combine.
__global__ void cumsum_kernel(const int* __restrict__ dur) {
    const int b = blockIdx.x;
    const int t = threadIdx.x;
    const int lane = t & 31, warp = t >> 5;

    int v = dur[b * SS + t];
    #pragma unroll
    for (int off = 1; off < 32; off <<= 1) {
        int u = __shfl_up_sync(0xffffffffu, v, off);
        if (lane >= off) v += u;
    }
    __shared__ int wsum[16];
    if (lane == 31) wsum[warp] = v;
    __syncthreads();
    if (warp == 0) {
        int w = (lane < 16) ? wsum[lane] : 0;
        #pragma unroll
        for (int off = 1; off < 16; off <<= 1) {
            int u = __shfl_up_sync(0xffffffffu, w, off);
            if (lane >= off) w += u;
        }
        if (lane < 16) wsum[lane] = w;
    }
    __syncthreads();
    const int base = (warp > 0) ? wsum[warp - 1] : 0;
    g_csum[b * SS + t] = base + v;
}

// One block (96 threads) per token. Token (b,t) with duration d writes frames
// [csum-d, csum) of batch b, each a contiguous 1536B float4 copy of its row.
// This is the op's definition: no searchsorted semantics to get wrong.
__global__ void scatter_kernel(const float* __restrict__ hidden,
                               const int* __restrict__ dur,
                               float* __restrict__ out, int L) {
    const int token = blockIdx.x;          // token == b*SS + t
    const int b = token >> 9;
    const int d = dur[token];
    if (d == 0) return;
    const int end = g_csum[token];         // inclusive cumsum
    const int start = end - d;             // exclusive cumsum
    const int i = threadIdx.x;             // 0..95, one float4 each

    const float4 v =
        reinterpret_cast<const float4*>(hidden + (size_t)token * DD)[i];
    float4* op =
        reinterpret_cast<float4*>(out + ((size_t)b * L + start) * DD) + i;
    for (int f = 0; f < d; f++) op[f * (DD / 4)] = v;
}

// Zero the padding region [total_b, L) per batch. One warp per frame; frames
// in the valid region exit immediately (d_out is poisoned, zeros required).
__global__ void pad_kernel(float* __restrict__ out, int L) {
    const int b = blockIdx.y;
    const int total = g_csum[b * SS + SS - 1];
    const int j = blockIdx.x * 4 + (threadIdx.x >> 5);
    if (j < total || j >= L) return;
    const int lane = threadIdx.x & 31;
    const float4 z = make_float4(0.f, 0.f, 0.f, 0.f);
    float4* op = reinterpret_cast<float4*>(out + ((size_t)b * L + j) * DD);
    op[lane] = z; op[lane + 32] = z; op[lane + 64] = z;
}

// Appended out_lengths (as float) plus zero-fill of any remaining tail slack.
__global__ void tail_kernel(float* __restrict__ tail, int n) {
    for (int i = threadIdx.x; i < n; i += blockDim.x)
        tail[i] = (i < BB) ? (float)g_csum[i * SS + SS - 1] : 0.f;
}

extern "C" void kernel_launch(void* const* d_in, const int* in_sizes, int n_in,
                              void* d_out, int out_size) {
    // Identify inputs by size, not by order: hidden has 16*512*384 = 3,145,728
    // elements; durations has 16*512 = 8,192.
    const float* hidden;
    const int*   dur;
    if (in_sizes[0] == BB * SS) {
        dur    = (const int*)d_in[0];
        hidden = (const float*)d_in[1];
    } else {
        hidden = (const float*)d_in[0];
        dur    = (const int*)d_in[1];
    }
    float* out = (float*)d_out;

    const int frame = BB * DD;                 // 6144 elements per frame-slab
    const int L = out_size / frame;            // frames per batch
    const int tail_n = out_size - L * frame;   // 16 if lengths appended, else 0

    cumsum_kernel<<<BB, SS>>>(dur);

    scatter_kernel<<<BB * SS, 96>>>(hidden, dur, out, L);

    dim3 pgrid((L + 3) / 4, BB);
    pad_kernel<<<pgrid, 128>>>(out, L);

    if (tail_n > 0) {
        tail_kernel<<<1, 256>>>(out + (size_t)BB * L * DD, tail_n);
    }
}

// round 5
// speedup vs baseline: 1.7733x; 1.7733x over previous
#include <cuda_runtime.h>
#include <cstddef>

#define BB 16
#define SS 512
#define DD 384
#define NT 96          // threads per block: 96 float4 lanes = one 1536B frame

// Reduce a per-thread partial across the 96-thread block; every thread gets
// the block total. 3 warps -> shfl reduce -> shared combine.
__device__ __forceinline__ int block_sum_96(int s) {
    const int lane = threadIdx.x & 31, warp = threadIdx.x >> 5;
    #pragma unroll
    for (int off = 16; off; off >>= 1) s += __shfl_down_sync(0xffffffffu, s, off);
    __shared__ int ws[3];
    if (lane == 0) ws[warp] = s;
    __syncthreads();
    return ws[0] + ws[1] + ws[2];
}

// Single fused kernel, three grid segments:
//   [0, 8192)                : token scatter (one block per token)
//   [8192, 8192+padBlocks)   : zero padding frames [total_b, L)
//   [8192+padBlocks]         : tail (appended out_lengths as float)
__global__ void __launch_bounds__(NT) fused_kernel(
    const float* __restrict__ hidden, const int* __restrict__ dur,
    float* __restrict__ out, int L, int padBlocks, int bpb, int tail_n) {
    const int tid = threadIdx.x;
    const int blk = blockIdx.x;

    if (blk < BB * SS) {
        // ---- token scatter: frames [excl, excl+d) of batch b <- hidden[b,t] ----
        const int token = blk;
        const int b = token >> 9;
        const int t = token & (SS - 1);
        const int d = dur[token];

        // exclusive prefix: sum dur[b*SS .. b*SS+t)  (dur is L1/L2 resident)
        int s = 0;
        const int* drow = dur + b * SS;
        for (int i = tid; i < t; i += NT) s += drow[i];
        const int excl = block_sum_96(s);

        if (d == 0) return;
        const float4 v =
            reinterpret_cast<const float4*>(hidden + (size_t)token * DD)[tid];
        float4* op =
            reinterpret_cast<float4*>(out + ((size_t)b * L + excl) * DD) + tid;
        for (int f = 0; f < d; f++) __stcs(op + f * (DD / 4), v);
        return;
    }

    if (blk < BB * SS + padBlocks) {
        // ---- padding: zero frames [total_b, L) of batch b ----
        const int pb = blk - BB * SS;
        const int b = pb / bpb;           // bpb pad blocks per batch
        const int pidx = pb - b * bpb;

        int s = 0;
        const int* drow = dur + b * SS;
        #pragma unroll
        for (int i = tid; i < SS; i += NT) s += drow[i];
        const int total = block_sum_96(s);

        const int warp = tid >> 5, lane = tid & 31;
        const float4 z = make_float4(0.f, 0.f, 0.f, 0.f);
        const int stride = bpb * 3;       // 3 warps per block
        for (int j = pidx * 3 + warp; j < L; j += stride) {
            if (j < total) continue;
            float4* op = reinterpret_cast<float4*>(out + ((size_t)b * L + j) * DD);
            __stcs(op + lane, z);
            __stcs(op + lane + 32, z);
            __stcs(op + lane + 64, z);
        }
        return;
    }

    // ---- tail: out_lengths per batch, as float, after the [B,L,D] tensor ----
    {
        float* tail = out + (size_t)BB * L * DD;
        const int warp = tid >> 5, lane = tid & 31;
        for (int b = warp; b < BB; b += 3) {
            const int* drow = dur + b * SS;
            int s = 0;
            #pragma unroll
            for (int i = lane; i < SS; i += 32) s += drow[i];
            #pragma unroll
            for (int off = 16; off; off >>= 1)
                s += __shfl_down_sync(0xffffffffu, s, off);
            if (lane == 0 && b < tail_n) tail[b] = (float)s;
        }
        // zero any tail slack beyond BB (defensive; normally tail_n == BB)
        for (int i = BB + tid; i < tail_n; i += NT) tail[i] = 0.f;
    }
}

extern "C" void kernel_launch(void* const* d_in, const int* in_sizes, int n_in,
                              void* d_out, int out_size) {
    // Identify inputs by element count, not order.
    const float* hidden;
    const int*   dur;
    if (in_sizes[0] == BB * SS) {
        dur    = (const int*)d_in[0];
        hidden = (const float*)d_in[1];
    } else {
        hidden = (const float*)d_in[0];
        dur    = (const int*)d_in[1];
    }
    float* out = (float*)d_out;

    const int frame = BB * DD;                 // 6144 floats per frame-slab
    const int L = out_size / frame;            // frames per batch
    const int tail_n = out_size - L * frame;   // 16 if lengths appended

    // pad blocks per batch: each block's 3 warps grid-stride over L frames
    const int bpb = (L + 47) / 48;             // ~16 frame-checks per warp
    const int padBlocks = bpb * BB;

    const int grid = BB * SS + padBlocks + 1;  // +1 tail block (always run;
                                               // writes nothing if tail_n==0)
    fused_kernel<<<grid, NT>>>(hidden, dur, out, L, padBlocks, bpb, tail_n);
}